// round 1
// baseline (speedup 1.0000x reference)
#include <cuda_runtime.h>
#include <cuda_bf16.h>
#include <cstdint>

// Problem constants
#define B_SZ   2048
#define D_SZ   128
#define C_SZ   100000
#define KNN    10

// Fused kernel tiling
#define SPLITC 18
#define TILES  87
#define SLICE  (TILES * 64)       // 5568; 18*5568 = 100224 >= 100000
#define BM     128
#define BN     64
#define SSTRIDE 136               // bf16 elems per smem row (128 + 8 pad -> conflict-free ldmatrix)
#define DSTRIDE 66                // float stride for dist tile

// Scratch (device globals; no allocation allowed)
__device__ float          g_enc_norm[B_SZ];
__device__ __nv_bfloat16  g_enc_bf16[B_SZ * D_SZ];
__device__ float          g_mem_norm[C_SZ];
__device__ __nv_bfloat16  g_mem_bf16[C_SZ * D_SZ];
__device__ float          g_partial[B_SZ * SPLITC * 2 * KNN];   // 360 candidates per row

// ---------------------------------------------------------------------------
// helpers
// ---------------------------------------------------------------------------
__device__ __forceinline__ uint32_t smem_u32(const void* p) {
    return (uint32_t)__cvta_generic_to_shared(p);
}

__device__ __forceinline__ void ldsm4(uint32_t& r0, uint32_t& r1, uint32_t& r2, uint32_t& r3,
                                      uint32_t addr) {
    asm volatile("ldmatrix.sync.aligned.m8n8.x4.shared.b16 {%0,%1,%2,%3}, [%4];\n"
                 : "=r"(r0), "=r"(r1), "=r"(r2), "=r"(r3) : "r"(addr));
}

__device__ __forceinline__ void mma16816(float* c, const uint32_t* a, const uint32_t* b) {
    asm volatile(
        "mma.sync.aligned.m16n8k16.row.col.f32.bf16.bf16.f32 "
        "{%0,%1,%2,%3},{%4,%5,%6,%7},{%8,%9},{%0,%1,%2,%3};\n"
        : "+f"(c[0]), "+f"(c[1]), "+f"(c[2]), "+f"(c[3])
        : "r"(a[0]), "r"(a[1]), "r"(a[2]), "r"(a[3]), "r"(b[0]), "r"(b[1]));
}

// ---------------------------------------------------------------------------
// Kernel A: encoder  enc = relu(state@W1+b1)@W2 + b2  (fp32), + bf16 copy + norms
// grid 256, block 128, 8 batch rows per CTA
// ---------------------------------------------------------------------------
__global__ void __launch_bounds__(128) enc_kernel(
    const float* __restrict__ state, const float* __restrict__ W1,
    const float* __restrict__ b1, const float* __restrict__ W2,
    const float* __restrict__ b2)
{
    __shared__ float s_buf[8][128];
    __shared__ float s_norm[8];
    const int t = threadIdx.x;
    const int row0 = blockIdx.x * 8;

    #pragma unroll
    for (int r = 0; r < 8; r++) s_buf[r][t] = state[(row0 + r) * D_SZ + t];
    if (t < 8) s_norm[t] = 0.f;
    __syncthreads();

    float acc[8];
    #pragma unroll
    for (int r = 0; r < 8; r++) acc[r] = 0.f;
    #pragma unroll 4
    for (int k = 0; k < D_SZ; k++) {
        float w = W1[k * D_SZ + t];
        #pragma unroll
        for (int r = 0; r < 8; r++) acc[r] = fmaf(s_buf[r][k], w, acc[r]);
    }
    __syncthreads();                 // done reading state
    {
        float bb = b1[t];
        #pragma unroll
        for (int r = 0; r < 8; r++) s_buf[r][t] = fmaxf(acc[r] + bb, 0.f);
    }
    __syncthreads();                 // h ready

    float acc2[8];
    #pragma unroll
    for (int r = 0; r < 8; r++) acc2[r] = 0.f;
    #pragma unroll 4
    for (int k = 0; k < D_SZ; k++) {
        float w = W2[k * D_SZ + t];
        #pragma unroll
        for (int r = 0; r < 8; r++) acc2[r] = fmaf(s_buf[r][k], w, acc2[r]);
    }
    {
        float b2v = b2[t];
        #pragma unroll
        for (int r = 0; r < 8; r++) {
            float e = acc2[r] + b2v;
            g_enc_bf16[(row0 + r) * D_SZ + t] = __float2bfloat16(e);
            atomicAdd(&s_norm[r], e * e);
        }
    }
    __syncthreads();
    if (t < 8) g_enc_norm[row0 + t] = s_norm[t];
}

// ---------------------------------------------------------------------------
// Kernel B: memory -> bf16 + row norms.  grid 25000, block 128 (4 rows/CTA)
// ---------------------------------------------------------------------------
__global__ void __launch_bounds__(128) prep_mem_kernel(const float* __restrict__ mem)
{
    const int warp = threadIdx.x >> 5, lane = threadIdx.x & 31;
    const int row = blockIdx.x * 4 + warp;
    if (row >= C_SZ) return;
    const float4 v = ((const float4*)(mem + (size_t)row * D_SZ))[lane];
    float nrm = v.x * v.x + v.y * v.y + v.z * v.z + v.w * v.w;
    __nv_bfloat162 p0 = __floats2bfloat162_rn(v.x, v.y);
    __nv_bfloat162 p1 = __floats2bfloat162_rn(v.z, v.w);
    __nv_bfloat162* dst = (__nv_bfloat162*)(g_mem_bf16 + (size_t)row * D_SZ + lane * 4);
    dst[0] = p0; dst[1] = p1;
    #pragma unroll
    for (int o = 16; o; o >>= 1) nrm += __shfl_xor_sync(0xffffffffu, nrm, o);
    if (lane == 0) g_mem_norm[row] = nrm;
}

// ---------------------------------------------------------------------------
// Kernel C: fused bf16 GEMM (enc @ mem^T) + distance + streaming top-10
// grid (SPLITC, 16), block 256.  Dynamic smem: enc tile + union(mem tile, dist tile)
// ---------------------------------------------------------------------------
__global__ void __launch_bounds__(256) knn_kernel()
{
    extern __shared__ char smem[];
    __nv_bfloat16* s_enc = (__nv_bfloat16*)smem;
    __nv_bfloat16* s_mem = (__nv_bfloat16*)(smem + BM * SSTRIDE * 2);
    float*         s_dist = (float*)(smem + BM * SSTRIDE * 2);   // aliases s_mem
    __shared__ float s_enorm[BM];
    __shared__ float s_mnorm[BN];

    const int tid  = threadIdx.x;
    const int bx   = blockIdx.x;          // C slice
    const int by   = blockIdx.y;          // batch tile
    const int row0 = by * BM;

    // load enc tile (persistent) + norms
    for (int idx = tid; idx < BM * 16; idx += 256) {
        int r = idx >> 4, c8 = idx & 15;
        ((uint4*)(s_enc + r * SSTRIDE))[c8] =
            ((const uint4*)(g_enc_bf16 + (size_t)(row0 + r) * D_SZ))[c8];
    }
    if (tid < BM) s_enorm[tid] = g_enc_norm[row0 + tid];

    const int warp = tid >> 5, lane = tid & 31;
    const int wm = warp & 3, wn = warp >> 2;         // warp tile: 32 rows x 32 cols
    const int lr = lane & 15, lc8 = lane >> 4;       // ldmatrix addressing
    const int g  = lane >> 2, tq = lane & 3;         // mma fragment coords
    const int srow = tid & 127, shalf = tid >> 7;    // scan assignment

    float best[KNN];
    #pragma unroll
    for (int i = 0; i < KNN; i++) best[i] = 3.0e37f;

    const int cbase = bx * SLICE;
    const uint32_t encBase = smem_u32(s_enc);
    const uint32_t memBase = smem_u32(s_mem);

    for (int t = 0; t < TILES; t++) {
        const int c0 = cbase + t * BN;
        __syncthreads();                               // prev scan done; union free
        // load mem tile (zero-pad out-of-range rows)
        for (int idx = tid; idx < BN * 16; idx += 256) {
            int r = idx >> 4, c8 = idx & 15;
            int c = c0 + r;
            uint4 val = make_uint4(0u, 0u, 0u, 0u);
            if (c < C_SZ) val = ((const uint4*)(g_mem_bf16 + (size_t)c * D_SZ))[c8];
            ((uint4*)(s_mem + r * SSTRIDE))[c8] = val;
        }
        if (tid < BN) {
            int c = c0 + tid;
            s_mnorm[tid] = (c < C_SZ) ? g_mem_norm[c] : 3.0e37f;
        }
        __syncthreads();                               // tile ready

        // ---- MMA: acc = enc_tile[warp rows] @ mem_tile[warp cols]^T
        float acc[2][4][4];
        #pragma unroll
        for (int mi = 0; mi < 2; mi++)
            #pragma unroll
            for (int ni = 0; ni < 4; ni++)
                #pragma unroll
                for (int q = 0; q < 4; q++) acc[mi][ni][q] = 0.f;

        #pragma unroll
        for (int ks = 0; ks < 8; ks++) {
            uint32_t a[2][4];
            #pragma unroll
            for (int mi = 0; mi < 2; mi++) {
                uint32_t addr = encBase +
                    ((wm * 32 + mi * 16 + lr) * SSTRIDE + ks * 16 + lc8 * 8) * 2;
                ldsm4(a[mi][0], a[mi][1], a[mi][2], a[mi][3], addr);
            }
            uint32_t bfr[4][2];
            #pragma unroll
            for (int nb = 0; nb < 2; nb++) {
                uint32_t q0, q1, q2, q3;
                uint32_t addr = memBase +
                    ((wn * 32 + nb * 16 + lr) * SSTRIDE + ks * 16 + lc8 * 8) * 2;
                ldsm4(q0, q1, q2, q3, addr);
                bfr[nb * 2 + 0][0] = q0; bfr[nb * 2 + 0][1] = q2;
                bfr[nb * 2 + 1][0] = q1; bfr[nb * 2 + 1][1] = q3;
            }
            #pragma unroll
            for (int mi = 0; mi < 2; mi++)
                #pragma unroll
                for (int ni = 0; ni < 4; ni++)
                    mma16816(acc[mi][ni], a[mi], bfr[ni]);
        }
        __syncthreads();                               // all mma reads of s_mem done

        // ---- epilogue: distance into s_dist (overwrites s_mem region)
        #pragma unroll
        for (int mi = 0; mi < 2; mi++) {
            int r0 = wm * 32 + mi * 16 + g;
            float e0 = s_enorm[r0], e1 = s_enorm[r0 + 8];
            #pragma unroll
            for (int ni = 0; ni < 4; ni++) {
                int col = wn * 32 + ni * 8 + 2 * tq;
                float m0 = s_mnorm[col], m1 = s_mnorm[col + 1];
                float* ap = acc[mi][ni];
                s_dist[r0 * DSTRIDE + col]           = sqrtf(fmaxf(e0 + m0 - 2.f * ap[0], 1e-12f));
                s_dist[r0 * DSTRIDE + col + 1]       = sqrtf(fmaxf(e0 + m1 - 2.f * ap[1], 1e-12f));
                s_dist[(r0 + 8) * DSTRIDE + col]     = sqrtf(fmaxf(e1 + m0 - 2.f * ap[2], 1e-12f));
                s_dist[(r0 + 8) * DSTRIDE + col + 1] = sqrtf(fmaxf(e1 + m1 - 2.f * ap[3], 1e-12f));
            }
        }
        __syncthreads();                               // dist tile ready

        // ---- scan: 2 threads per row, 32 cols each, register top-10
        const float* dr = s_dist + srow * DSTRIDE + shalf * 32;
        #pragma unroll 8
        for (int c2 = 0; c2 < 32; c2++) {
            float d = dr[c2];
            if (d < best[KNN - 1]) {
                best[KNN - 1] = d;
                #pragma unroll
                for (int i = KNN - 1; i > 0; i--) {
                    if (best[i] < best[i - 1]) {
                        float tv = best[i - 1]; best[i - 1] = best[i]; best[i] = tv;
                    }
                }
            }
        }
    }

    // write partial top-10s
    const int rg = row0 + srow;
    float* dst = g_partial + ((size_t)(rg * SPLITC + bx) * 2 + shalf) * KNN;
    #pragma unroll
    for (int i = 0; i < KNN; i++) dst[i] = best[i];
}

// ---------------------------------------------------------------------------
// Kernel D: merge 360 candidates/row -> mean of 10 smallest.  1 warp per row.
// grid 256, block 256 (8 warps)
// ---------------------------------------------------------------------------
__global__ void __launch_bounds__(256) merge_kernel(float* __restrict__ out)
{
    const int warp = threadIdx.x >> 5, lane = threadIdx.x & 31;
    const int row = blockIdx.x * 8 + warp;
    const int NC = SPLITC * 2 * KNN;                  // 360
    const float* src = g_partial + (size_t)row * NC;

    float v[12];
    #pragma unroll
    for (int j = 0; j < 12; j++) {
        int idx = j * 32 + lane;
        v[j] = (idx < NC) ? src[idx] : 3.0e37f;
    }
    float sum = 0.f;
    for (int it = 0; it < KNN; it++) {
        float lm = v[0];
        #pragma unroll
        for (int j = 1; j < 12; j++) lm = fminf(lm, v[j]);
        float gm = lm;
        #pragma unroll
        for (int o = 16; o; o >>= 1) gm = fminf(gm, __shfl_xor_sync(0xffffffffu, gm, o));
        sum += gm;
        unsigned mask = __ballot_sync(0xffffffffu, lm == gm);
        int leader = __ffs(mask) - 1;
        if (lane == leader) {
            bool done = false;
            #pragma unroll
            for (int j = 0; j < 12; j++) {
                if (!done && v[j] == gm) { v[j] = 3.0e37f; done = true; }
            }
        }
    }
    if (lane == 0) out[row] = sum * (1.0f / KNN);
}

// ---------------------------------------------------------------------------
// launch
// ---------------------------------------------------------------------------
extern "C" void kernel_launch(void* const* d_in, const int* in_sizes, int n_in,
                              void* d_out, int out_size)
{
    (void)in_sizes; (void)n_in; (void)out_size;
    const float* state  = (const float*)d_in[0];
    const float* W1     = (const float*)d_in[1];
    const float* b1     = (const float*)d_in[2];
    const float* W2     = (const float*)d_in[3];
    const float* b2     = (const float*)d_in[4];
    const float* memory = (const float*)d_in[5];
    float* out = (float*)d_out;

    const int smemC = BM * SSTRIDE * 2 + BM * DSTRIDE * 4;   // 68608 bytes
    cudaFuncSetAttribute(knn_kernel, cudaFuncAttributeMaxDynamicSharedMemorySize, smemC);

    enc_kernel<<<B_SZ / 8, 128>>>(state, W1, b1, W2, b2);
    prep_mem_kernel<<<C_SZ / 4, 128>>>(memory);
    knn_kernel<<<dim3(SPLITC, B_SZ / BM), 256, smemC>>>();
    merge_kernel<<<B_SZ / 8 / 32 * 32 ? (B_SZ / 8) : 1, 256>>>(out);
}

// round 2
// speedup vs baseline: 1.6030x; 1.6030x over previous
#include <cuda_runtime.h>
#include <cuda_bf16.h>
#include <cstdint>

// Problem constants
#define B_SZ   2048
#define D_SZ   128
#define C_SZ   100000
#define KNN    10

// Fused kernel tiling
#define SPLITC 18
#define TILES  87
#define SLICE  (TILES * 64)       // 5568; 18*5568 = 100224 >= 100000
#define BM     128
#define BN     64
#define SSTRIDE 136               // bf16 elems per smem row (128 + 8 pad)
#define TILEBYTES (BN * SSTRIDE * 2)   // 17408

// Scratch (device globals; no allocation allowed)
__device__ float          g_enc_norm[B_SZ];
__device__ __nv_bfloat16  g_enc_bf16[B_SZ * D_SZ];
__device__ float          g_mem_norm[C_SZ];
__device__ __nv_bfloat16  g_mem_bf16[C_SZ * D_SZ];
__device__ float          g_partial[(size_t)B_SZ * SPLITC * 4 * KNN];  // 720 cand/row

// ---------------------------------------------------------------------------
// helpers
// ---------------------------------------------------------------------------
__device__ __forceinline__ uint32_t smem_u32(const void* p) {
    return (uint32_t)__cvta_generic_to_shared(p);
}

__device__ __forceinline__ void ldsm4(uint32_t& r0, uint32_t& r1, uint32_t& r2, uint32_t& r3,
                                      uint32_t addr) {
    asm volatile("ldmatrix.sync.aligned.m8n8.x4.shared.b16 {%0,%1,%2,%3}, [%4];\n"
                 : "=r"(r0), "=r"(r1), "=r"(r2), "=r"(r3) : "r"(addr));
}

__device__ __forceinline__ void mma16816(float* c, const uint32_t* a, const uint32_t* b) {
    asm volatile(
        "mma.sync.aligned.m16n8k16.row.col.f32.bf16.bf16.f32 "
        "{%0,%1,%2,%3},{%4,%5,%6,%7},{%8,%9},{%0,%1,%2,%3};\n"
        : "+f"(c[0]), "+f"(c[1]), "+f"(c[2]), "+f"(c[3])
        : "r"(a[0]), "r"(a[1]), "r"(a[2]), "r"(a[3]), "r"(b[0]), "r"(b[1]));
}

__device__ __forceinline__ void cp_async16(uint32_t saddr, const void* gptr, int srcbytes) {
    asm volatile("cp.async.cg.shared.global [%0], [%1], 16, %2;\n"
                 :: "r"(saddr), "l"(gptr), "r"(srcbytes));
}
__device__ __forceinline__ void cp_commit() { asm volatile("cp.async.commit_group;\n"); }
__device__ __forceinline__ void cp_wait0()  { asm volatile("cp.async.wait_group 0;\n"); }

__device__ __forceinline__ void topk_insert(float* best, float v) {
    if (v < best[KNN - 1]) {
        best[KNN - 1] = v;
        #pragma unroll
        for (int i = KNN - 1; i > 0; i--) {
            float lo = fminf(best[i - 1], best[i]);
            float hi = fmaxf(best[i - 1], best[i]);
            best[i - 1] = lo; best[i] = hi;
        }
    }
}

// ---------------------------------------------------------------------------
// Kernel A: encoder  enc = relu(state@W1+b1)@W2 + b2  (fp32), + bf16 copy + norms
// ---------------------------------------------------------------------------
__global__ void __launch_bounds__(128) enc_kernel(
    const float* __restrict__ state, const float* __restrict__ W1,
    const float* __restrict__ b1, const float* __restrict__ W2,
    const float* __restrict__ b2)
{
    __shared__ float s_buf[8][128];
    __shared__ float s_norm[8];
    const int t = threadIdx.x;
    const int row0 = blockIdx.x * 8;

    #pragma unroll
    for (int r = 0; r < 8; r++) s_buf[r][t] = state[(row0 + r) * D_SZ + t];
    if (t < 8) s_norm[t] = 0.f;
    __syncthreads();

    float acc[8];
    #pragma unroll
    for (int r = 0; r < 8; r++) acc[r] = 0.f;
    #pragma unroll 4
    for (int k = 0; k < D_SZ; k++) {
        float w = W1[k * D_SZ + t];
        #pragma unroll
        for (int r = 0; r < 8; r++) acc[r] = fmaf(s_buf[r][k], w, acc[r]);
    }
    __syncthreads();
    {
        float bb = b1[t];
        #pragma unroll
        for (int r = 0; r < 8; r++) s_buf[r][t] = fmaxf(acc[r] + bb, 0.f);
    }
    __syncthreads();

    float acc2[8];
    #pragma unroll
    for (int r = 0; r < 8; r++) acc2[r] = 0.f;
    #pragma unroll 4
    for (int k = 0; k < D_SZ; k++) {
        float w = W2[k * D_SZ + t];
        #pragma unroll
        for (int r = 0; r < 8; r++) acc2[r] = fmaf(s_buf[r][k], w, acc2[r]);
    }
    {
        float b2v = b2[t];
        #pragma unroll
        for (int r = 0; r < 8; r++) {
            float e = acc2[r] + b2v;
            g_enc_bf16[(row0 + r) * D_SZ + t] = __float2bfloat16(e);
            atomicAdd(&s_norm[r], e * e);
        }
    }
    __syncthreads();
    if (t < 8) g_enc_norm[row0 + t] = s_norm[t];
}

// ---------------------------------------------------------------------------
// Kernel B: memory -> bf16 + row norms.
// ---------------------------------------------------------------------------
__global__ void __launch_bounds__(128) prep_mem_kernel(const float* __restrict__ mem)
{
    const int warp = threadIdx.x >> 5, lane = threadIdx.x & 31;
    const int row = blockIdx.x * 4 + warp;
    if (row >= C_SZ) return;
    const float4 v = ((const float4*)(mem + (size_t)row * D_SZ))[lane];
    float nrm = v.x * v.x + v.y * v.y + v.z * v.z + v.w * v.w;
    __nv_bfloat162 p0 = __floats2bfloat162_rn(v.x, v.y);
    __nv_bfloat162 p1 = __floats2bfloat162_rn(v.z, v.w);
    __nv_bfloat162* dst = (__nv_bfloat162*)(g_mem_bf16 + (size_t)row * D_SZ + lane * 4);
    dst[0] = p0; dst[1] = p1;
    #pragma unroll
    for (int o = 16; o; o >>= 1) nrm += __shfl_xor_sync(0xffffffffu, nrm, o);
    if (lane == 0) g_mem_norm[row] = nrm;
}

// ---------------------------------------------------------------------------
// Kernel C: fused bf16 GEMM + squared-distance screening + register top-10
// grid (SPLITC, 16), block 256.  Warp tile = 16 rows x 64 cols.
// Double-buffered cp.async mem tiles, one barrier per tile, A-frags hoisted.
// ---------------------------------------------------------------------------
__global__ void __launch_bounds__(256, 2) knn_kernel()
{
    extern __shared__ char smem[];
    __nv_bfloat16* s_enc = (__nv_bfloat16*)smem;                   // 34816 B
    char*          s_mem = smem + BM * SSTRIDE * 2;                // 2 x 17408 B
    __shared__ float s_enorm[BM];
    __shared__ float s_mnorm[2][BN];

    const int tid  = threadIdx.x;
    const int bx   = blockIdx.x;          // C slice
    const int by   = blockIdx.y;          // batch tile
    const int row0 = by * BM;
    const int cbase = bx * SLICE;

    // ---- persistent enc tile + norms
    for (int idx = tid; idx < BM * 16; idx += 256) {
        int r = idx >> 4, c8 = idx & 15;
        ((uint4*)(s_enc + r * SSTRIDE))[c8] =
            ((const uint4*)(g_enc_bf16 + (size_t)(row0 + r) * D_SZ))[c8];
    }
    if (tid < BM) s_enorm[tid] = g_enc_norm[row0 + tid];

    const uint32_t encBase = smem_u32(s_enc);
    const uint32_t memBase = smem_u32(s_mem);

    // ---- preload tile 0
    {
        #pragma unroll
        for (int i = 0; i < 4; i++) {
            int idx = i * 256 + tid;
            int r = idx >> 4, c8 = idx & 15;
            int c = cbase + r;
            int cc = (c < C_SZ) ? c : 0;
            cp_async16(memBase + (r * SSTRIDE + c8 * 8) * 2,
                       g_mem_bf16 + (size_t)cc * D_SZ + c8 * 8,
                       (c < C_SZ) ? 16 : 0);
        }
        if (tid < BN) {
            int c = cbase + tid;
            s_mnorm[0][tid] = (c < C_SZ) ? g_mem_norm[c] : 3.0e37f;
        }
        cp_commit();
    }
    __syncthreads();    // enc tile visible

    const int warp = tid >> 5, lane = tid & 31;
    const int lr = lane & 15, lc8 = lane >> 4;
    const int g  = lane >> 2, tq = lane & 3;

    // ---- hoist A fragments (tile-invariant): 8 k-steps x 4 regs
    uint32_t afrag[8][4];
    #pragma unroll
    for (int ks = 0; ks < 8; ks++) {
        uint32_t addr = encBase + ((warp * 16 + lr) * SSTRIDE + ks * 16 + lc8 * 8) * 2;
        ldsm4(afrag[ks][0], afrag[ks][1], afrag[ks][2], afrag[ks][3], addr);
    }

    float best0[KNN], best1[KNN];
    #pragma unroll
    for (int i = 0; i < KNN; i++) { best0[i] = 3.0e37f; best1[i] = 3.0e37f; }

    for (int t = 0; t < TILES; t++) {
        cp_wait0();
        __syncthreads();          // tile t data + mnorm visible; prev iter done
        const int cur = t & 1;

        // ---- issue tile t+1 copy (overlaps MMA below)
        if (t + 1 < TILES) {
            const int c0n = cbase + (t + 1) * BN;
            const uint32_t nbuf = memBase + (1 - cur) * TILEBYTES;
            #pragma unroll
            for (int i = 0; i < 4; i++) {
                int idx = i * 256 + tid;
                int r = idx >> 4, c8 = idx & 15;
                int c = c0n + r;
                int cc = (c < C_SZ) ? c : 0;
                cp_async16(nbuf + (r * SSTRIDE + c8 * 8) * 2,
                           g_mem_bf16 + (size_t)cc * D_SZ + c8 * 8,
                           (c < C_SZ) ? 16 : 0);
            }
            if (tid < BN) {
                int c = c0n + tid;
                s_mnorm[1 - cur][tid] = (c < C_SZ) ? g_mem_norm[c] : 3.0e37f;
            }
        }
        cp_commit();

        // ---- MMA: 16 rows x 64 cols per warp
        float acc[8][4];
        #pragma unroll
        for (int ni = 0; ni < 8; ni++)
            #pragma unroll
            for (int q = 0; q < 4; q++) acc[ni][q] = 0.f;

        const uint32_t curBase = memBase + cur * TILEBYTES;
        #pragma unroll
        for (int ks = 0; ks < 8; ks++) {
            #pragma unroll
            for (int nb = 0; nb < 4; nb++) {
                uint32_t q0, q1, q2, q3;
                ldsm4(q0, q1, q2, q3,
                      curBase + ((nb * 16 + lr) * SSTRIDE + ks * 16 + lc8 * 8) * 2);
                uint32_t be[2] = {q0, q2};
                uint32_t bo[2] = {q1, q3};
                mma16816(acc[nb * 2 + 0], afrag[ks], be);
                mma16816(acc[nb * 2 + 1], afrag[ks], bo);
            }
        }

        // ---- epilogue: screened value s = ||m||^2 - 2*dot  (no sqrt, registers only)
        #pragma unroll
        for (int ni = 0; ni < 8; ni++) {
            int c = ni * 8 + 2 * tq;
            float m0 = s_mnorm[cur][c], m1 = s_mnorm[cur][c + 1];
            topk_insert(best0, fmaf(-2.f, acc[ni][0], m0));
            topk_insert(best0, fmaf(-2.f, acc[ni][1], m1));
            topk_insert(best1, fmaf(-2.f, acc[ni][2], m0));
            topk_insert(best1, fmaf(-2.f, acc[ni][3], m1));
        }
    }

    // ---- write partial top-10 (squared dist = enorm + screened)
    const int r0 = warp * 16 + g;
    const float e0 = s_enorm[r0], e1 = s_enorm[r0 + 8];
    float* dst0 = g_partial + ((size_t)((row0 + r0) * SPLITC + bx) * 4 + tq) * KNN;
    float* dst1 = g_partial + ((size_t)((row0 + r0 + 8) * SPLITC + bx) * 4 + tq) * KNN;
    #pragma unroll
    for (int i = 0; i < KNN; i++) {
        dst0[i] = e0 + best0[i];
        dst1[i] = e1 + best1[i];
    }
}

// ---------------------------------------------------------------------------
// Kernel D: merge 720 squared-dist candidates/row -> mean of 10 smallest sqrt.
// 1 warp per row, grid 256, block 256 (8 warps)
// ---------------------------------------------------------------------------
__global__ void __launch_bounds__(256) merge_kernel(float* __restrict__ out)
{
    const int warp = threadIdx.x >> 5, lane = threadIdx.x & 31;
    const int row = blockIdx.x * 8 + warp;
    const int NC = SPLITC * 4 * KNN;                  // 720
    const float* src = g_partial + (size_t)row * NC;

    float v[23];
    #pragma unroll
    for (int j = 0; j < 23; j++) {
        int idx = j * 32 + lane;
        v[j] = (idx < NC) ? src[idx] : 3.0e37f;
    }
    float sum = 0.f;
    for (int it = 0; it < KNN; it++) {
        float lm = v[0];
        #pragma unroll
        for (int j = 1; j < 23; j++) lm = fminf(lm, v[j]);
        float gm = lm;
        #pragma unroll
        for (int o = 16; o; o >>= 1) gm = fminf(gm, __shfl_xor_sync(0xffffffffu, gm, o));
        sum += sqrtf(fmaxf(gm, 1e-12f));
        unsigned mask = __ballot_sync(0xffffffffu, lm == gm);
        int leader = __ffs(mask) - 1;
        if (lane == leader) {
            bool done = false;
            #pragma unroll
            for (int j = 0; j < 23; j++) {
                if (!done && v[j] == gm) { v[j] = 3.0e37f; done = true; }
            }
        }
    }
    if (lane == 0) out[row] = sum * (1.0f / KNN);
}

// ---------------------------------------------------------------------------
// launch
// ---------------------------------------------------------------------------
extern "C" void kernel_launch(void* const* d_in, const int* in_sizes, int n_in,
                              void* d_out, int out_size)
{
    (void)in_sizes; (void)n_in; (void)out_size;
    const float* state  = (const float*)d_in[0];
    const float* W1     = (const float*)d_in[1];
    const float* b1     = (const float*)d_in[2];
    const float* W2     = (const float*)d_in[3];
    const float* b2     = (const float*)d_in[4];
    const float* memory = (const float*)d_in[5];
    float* out = (float*)d_out;

    const int smemC = BM * SSTRIDE * 2 + 2 * TILEBYTES;   // 69632 bytes
    cudaFuncSetAttribute(knn_kernel, cudaFuncAttributeMaxDynamicSharedMemorySize, smemC);

    enc_kernel<<<B_SZ / 8, 128>>>(state, W1, b1, W2, b2);
    prep_mem_kernel<<<C_SZ / 4, 128>>>(memory);
    knn_kernel<<<dim3(SPLITC, B_SZ / BM), 256, smemC>>>();
    merge_kernel<<<B_SZ / 8, 256>>>(out);
}